// round 14
// baseline (speedup 1.0000x reference)
#include <cuda_runtime.h>
#include <cuda_bf16.h>
#include <math.h>

#define Bc   4
#define Pc   1024
#define Dc   512
#define Hc   8
#define DKc  64
#define HALFW 32
#define CONCAT_P (2*Pc)

#define M_PROJ (Bc * Pc)        // 4096
#define M_OUT  (Bc * CONCAT_P)  // 8192
#define NROWS (2 * Bc * Hc * Pc)   // 65536 dense-A rows (A1|A2)

__device__ __nv_bfloat16 g_Ahi[3 * M_PROJ * Dc];
__device__ __nv_bfloat16 g_Alo[3 * M_PROJ * Dc];
__device__ __nv_bfloat16 g_Bhi[4 * Dc * Dc];        // weights [n][k]
__device__ __nv_bfloat16 g_Blo[4 * Dc * Dc];
__device__ __nv_bfloat16 g_QKVhi[3 * M_PROJ * Dc];
__device__ __nv_bfloat16 g_QKVlo[3 * M_PROJ * Dc];
__device__ __nv_bfloat16 g_Chi[M_OUT * Dc];
__device__ __nv_bfloat16 g_Clo[M_OUT * Dc];
__device__ float g_Pwin[(long long)NROWS * 128];    // compact normalized windows

// ---------------------------------------------------------------------------
__device__ __forceinline__ void split_bf16(float v, __nv_bfloat16& hi, __nv_bfloat16& lo)
{
    hi = __float2bfloat16(v);
    lo = __float2bfloat16(v - __bfloat162float(hi));
}

__global__ void split_a_kernel(const float* __restrict__ s0, const float* __restrict__ s1,
                               const float* __restrict__ s2,
                               __nv_bfloat16* __restrict__ hi, __nv_bfloat16* __restrict__ lo)
{
    int z = blockIdx.z;
    const float* src = (z == 0) ? s0 : (z == 1) ? s1 : s2;
    long long base = (long long)z * M_PROJ * Dc;
    long long n4 = (long long)M_PROJ * Dc / 4;
    long long idx = (long long)blockIdx.x * blockDim.x + threadIdx.x;
    long long stride = (long long)gridDim.x * blockDim.x;
    for (long long i = idx; i < n4; i += stride) {
        float4 v = ((const float4*)src)[i];
        __nv_bfloat16 h[4], l[4];
        split_bf16(v.x, h[0], l[0]);
        split_bf16(v.y, h[1], l[1]);
        split_bf16(v.z, h[2], l[2]);
        split_bf16(v.w, h[3], l[3]);
        long long o = base + i * 4;
        *(__nv_bfloat162*)&hi[o]     = __nv_bfloat162(h[0], h[1]);
        *(__nv_bfloat162*)&hi[o + 2] = __nv_bfloat162(h[2], h[3]);
        *(__nv_bfloat162*)&lo[o]     = __nv_bfloat162(l[0], l[1]);
        *(__nv_bfloat162*)&lo[o + 2] = __nv_bfloat162(l[2], l[3]);
    }
}

__global__ void split_b_kernel(const float* __restrict__ w0, const float* __restrict__ w1,
                               const float* __restrict__ w2, const float* __restrict__ w3,
                               __nv_bfloat16* __restrict__ hi, __nv_bfloat16* __restrict__ lo)
{
    __shared__ float t[32][33];
    int z = blockIdx.z;
    const float* W = (z == 0) ? w0 : (z == 1) ? w1 : (z == 2) ? w2 : w3;
    long long base = (long long)z * Dc * Dc;
    int n0 = blockIdx.x * 32;
    int k0 = blockIdx.y * 32;
    int tx = threadIdx.x, ty = threadIdx.y;
#pragma unroll
    for (int i = 0; i < 4; i++)
        t[ty + i * 8][tx] = W[(long long)(k0 + ty + i * 8) * Dc + n0 + tx];
    __syncthreads();
#pragma unroll
    for (int i = 0; i < 4; i++) {
        float v = t[tx][ty + i * 8];
        long long o = base + (long long)(n0 + ty + i * 8) * Dc + k0 + tx;
        __nv_bfloat16 h, l;
        split_bf16(v, h, l);
        hi[o] = h;
        lo[o] = l;
    }
}

// ---------------------------------------------------------------------------
// mma / ldmatrix helpers
// ---------------------------------------------------------------------------
__device__ __forceinline__ void mma_bf16(float* d, const unsigned* a, const unsigned* b)
{
    asm volatile(
        "mma.sync.aligned.m16n8k16.row.col.f32.bf16.bf16.f32 "
        "{%0,%1,%2,%3}, {%4,%5,%6,%7}, {%8,%9}, {%0,%1,%2,%3};"
        : "+f"(d[0]), "+f"(d[1]), "+f"(d[2]), "+f"(d[3])
        : "r"(a[0]), "r"(a[1]), "r"(a[2]), "r"(a[3]), "r"(b[0]), "r"(b[1]));
}

__device__ __forceinline__ void ldmatrix_x4(unsigned* r, unsigned addr)
{
    asm volatile("ldmatrix.sync.aligned.m8n8.x4.shared.b16 {%0,%1,%2,%3}, [%4];"
        : "=r"(r[0]), "=r"(r[1]), "=r"(r[2]), "=r"(r[3]) : "r"(addr));
}

__device__ __forceinline__ void ldmatrix_x4_trans(unsigned* r, unsigned addr)
{
    asm volatile("ldmatrix.sync.aligned.m8n8.x4.trans.shared.b16 {%0,%1,%2,%3}, [%4];"
        : "=r"(r[0]), "=r"(r[1]), "=r"(r[2]), "=r"(r[3]) : "r"(addr));
}

__device__ __forceinline__ void cpasync16(void* dst_sh, const void* src)
{
    unsigned sh = (unsigned)__cvta_generic_to_shared(dst_sh);
    asm volatile("cp.async.cg.shared.global [%0], [%1], 16;\n" :: "r"(sh), "l"(src));
}

// ---------------------------------------------------------------------------
// Shared GEMM mainloop body (bf16-split, ldmatrix fragments).
// Computes a 128x128 tile; acc[4][4][4] result in registers.
// ---------------------------------------------------------------------------
#define GS_STRIDE 40
#define GS_TILE   (128 * GS_STRIDE)
#define GS_STAGE  (4 * GS_TILE)
#define GEMM_SMEM_BYTES (2 * GS_STAGE * 2)   // 81920

__device__ __forceinline__
void gemm_mainloop(const __nv_bfloat16* Ah, const __nv_bfloat16* Al,
                   const __nv_bfloat16* Bh, const __nv_bfloat16* Bl,
                   __nv_bfloat16* smem, unsigned smem_u32,
                   int row0, int col0, float acc[4][4][4])
{
    int tid  = threadIdx.x;
    int lane = tid & 31;
    int warp = tid >> 5;
    int wm = (warp & 1) * 64;
    int wn = (warp >> 1) * 32;

    int cp_arr[8], cp_row[8], cp_c[8];
#pragma unroll
    for (int i = 0; i < 8; i++) {
        cp_arr[i] = i >> 1;
        int idx2 = ((i & 1) << 8) + tid;
        cp_row[i] = idx2 >> 2;
        cp_c[i] = (idx2 & 3) * 8;
    }

    const int nIt = Dc / 32;

    auto load_stage = [&](int it, int s) {
        __nv_bfloat16* st = smem + s * GS_STAGE;
        int k0 = it * 32;
#pragma unroll
        for (int i = 0; i < 8; i++) {
            const __nv_bfloat16* src;
            int row = cp_row[i];
            int c = cp_c[i];
            if (cp_arr[i] == 0)      src = Ah + (long long)(row0 + row) * Dc + k0 + c;
            else if (cp_arr[i] == 1) src = Al + (long long)(row0 + row) * Dc + k0 + c;
            else if (cp_arr[i] == 2) src = Bh + (long long)(col0 + row) * Dc + k0 + c;
            else                     src = Bl + (long long)(col0 + row) * Dc + k0 + c;
            cpasync16(st + cp_arr[i] * GS_TILE + row * GS_STRIDE + c, src);
        }
        asm volatile("cp.async.commit_group;\n" ::);
    };

    load_stage(0, 0);

    for (int it = 0; it < nIt; it++) {
        int buf = it & 1;
        if (it + 1 < nIt) {
            load_stage(it + 1, buf ^ 1);
            asm volatile("cp.async.wait_group 1;\n" ::);
        } else {
            asm volatile("cp.async.wait_group 0;\n" ::);
        }
        __syncthreads();

        unsigned stage_base = smem_u32 + (unsigned)(buf * GS_STAGE * 2);
        unsigned uAh = stage_base;
        unsigned uAl = stage_base + GS_TILE * 2;
        unsigned uBh = stage_base + 2 * GS_TILE * 2;
        unsigned uBl = stage_base + 3 * GS_TILE * 2;

#pragma unroll
        for (int kk = 0; kk < 32; kk += 16) {
            unsigned a_h[4][4], a_l[4][4];
#pragma unroll
            for (int im = 0; im < 4; im++) {
                int row = wm + im * 16 + (lane & 15);
                int col = kk + 8 * (lane >> 4);
                unsigned off = (unsigned)(row * GS_STRIDE + col) * 2;
                ldmatrix_x4(a_h[im], uAh + off);
                ldmatrix_x4(a_l[im], uAl + off);
            }
            unsigned b_h[4][2], b_l[4][2];
#pragma unroll
            for (int nt = 0; nt < 2; nt++) {
                int row = wn + nt * 16 + (lane & 7) + 8 * (lane >> 4);
                int col = kk + 8 * ((lane >> 3) & 1);
                unsigned off = (unsigned)(row * GS_STRIDE + col) * 2;
                unsigned th[4], tl[4];
                ldmatrix_x4(th, uBh + off);
                ldmatrix_x4(tl, uBl + off);
                b_h[2*nt][0] = th[0];   b_h[2*nt][1] = th[1];
                b_h[2*nt+1][0] = th[2]; b_h[2*nt+1][1] = th[3];
                b_l[2*nt][0] = tl[0];   b_l[2*nt][1] = tl[1];
                b_l[2*nt+1][0] = tl[2]; b_l[2*nt+1][1] = tl[3];
            }
#pragma unroll
            for (int im = 0; im < 4; im++)
#pragma unroll
                for (int in_ = 0; in_ < 4; in_++) {
                    mma_bf16(acc[im][in_], a_h[im], b_h[in_]);
                    mma_bf16(acc[im][in_], a_h[im], b_l[in_]);
                    mma_bf16(acc[im][in_], a_l[im], b_h[in_]);
                }
        }
        __syncthreads();
    }
}

// ---------------------------------------------------------------------------
// Projection GEMM: 3 z-slices, epilogue writes bf16 hi/lo QKV
// ---------------------------------------------------------------------------
__global__ __launch_bounds__(256)
void gemm_proj_kernel(const __nv_bfloat16* __restrict__ Ah, const __nv_bfloat16* __restrict__ Al,
                      const __nv_bfloat16* __restrict__ Bh, const __nv_bfloat16* __restrict__ Bl,
                      __nv_bfloat16* Chi, __nv_bfloat16* Clo,
                      const float* b0, const float* b1, const float* b2)
{
    extern __shared__ __nv_bfloat16 smem[];
    unsigned smem_u32 = (unsigned)__cvta_generic_to_shared(smem);
    int z = blockIdx.z;
    const long long aStride = (long long)M_PROJ * Dc;
    const long long bStride = (long long)Dc * Dc;
    Ah += z * aStride; Al += z * aStride;
    Bh += z * bStride; Bl += z * bStride;
    const float* bias = (z == 0) ? b0 : (z == 1) ? b1 : b2;

    int lane = threadIdx.x & 31;
    int warp = threadIdx.x >> 5;
    int wm = (warp & 1) * 64;
    int wn = (warp >> 1) * 32;
    int row0 = blockIdx.y * 128;
    int col0 = blockIdx.x * 128;

    float acc[4][4][4];
#pragma unroll
    for (int im = 0; im < 4; im++)
#pragma unroll
        for (int in_ = 0; in_ < 4; in_++)
#pragma unroll
            for (int r = 0; r < 4; r++) acc[im][in_][r] = 0.f;

    gemm_mainloop(Ah, Al, Bh, Bl, smem, smem_u32, row0, col0, acc);

    long long cb = (long long)z * aStride;
#pragma unroll
    for (int im = 0; im < 4; im++) {
#pragma unroll
        for (int in_ = 0; in_ < 4; in_++) {
            int row = row0 + wm + im * 16 + (lane >> 2);
            int col = col0 + wn + in_ * 8 + 2 * (lane & 3);
            float2 bv = *(const float2*)&bias[col];
            float o0 = acc[im][in_][0] + bv.x, o1 = acc[im][in_][1] + bv.y;
            float o2 = acc[im][in_][2] + bv.x, o3 = acc[im][in_][3] + bv.y;
            __nv_bfloat16 h0, l0, h1, l1, h2, l2, h3, l3;
            split_bf16(o0, h0, l0); split_bf16(o1, h1, l1);
            split_bf16(o2, h2, l2); split_bf16(o3, h3, l3);
            *(__nv_bfloat162*)&Chi[cb + (long long)row * Dc + col]       = __nv_bfloat162(h0, h1);
            *(__nv_bfloat162*)&Clo[cb + (long long)row * Dc + col]       = __nv_bfloat162(l0, l1);
            *(__nv_bfloat162*)&Chi[cb + (long long)(row + 8) * Dc + col] = __nv_bfloat162(h2, h3);
            *(__nv_bfloat162*)&Clo[cb + (long long)(row + 8) * Dc + col] = __nv_bfloat162(l2, l3);
        }
    }
}

// ---------------------------------------------------------------------------
// Fused out-GEMM (z==0) + dense-A writer (z>=1): concurrent roles in 1 launch.
// grid = (4, 64, 1 + W). Writer covers NROWS rows, 4 per block.
// ---------------------------------------------------------------------------
__global__ __launch_bounds__(256)
void outgemm_writeA_kernel(const __nv_bfloat16* __restrict__ Ah, const __nv_bfloat16* __restrict__ Al,
                           const __nv_bfloat16* __restrict__ Bh, const __nv_bfloat16* __restrict__ Bl,
                           float* __restrict__ C, const float* __restrict__ bias,
                           const float* __restrict__ Pwin, float* __restrict__ A1)
{
    extern __shared__ __nv_bfloat16 smem[];
    if (blockIdx.z == 0) {
        unsigned smem_u32 = (unsigned)__cvta_generic_to_shared(smem);
        int lane = threadIdx.x & 31;
        int warp = threadIdx.x >> 5;
        int wm = (warp & 1) * 64;
        int wn = (warp >> 1) * 32;
        int row0 = blockIdx.y * 128;
        int col0 = blockIdx.x * 128;

        float acc[4][4][4];
#pragma unroll
        for (int im = 0; im < 4; im++)
#pragma unroll
            for (int in_ = 0; in_ < 4; in_++)
#pragma unroll
                for (int r = 0; r < 4; r++) acc[im][in_][r] = 0.f;

        gemm_mainloop(Ah, Al, Bh, Bl, smem, smem_u32, row0, col0, acc);

#pragma unroll
        for (int im = 0; im < 4; im++) {
#pragma unroll
            for (int in_ = 0; in_ < 4; in_++) {
                int row = row0 + wm + im * 16 + (lane >> 2);
                int col = col0 + wn + in_ * 8 + 2 * (lane & 3);
                float2 bv = *(const float2*)&bias[col];
                *(float2*)&C[(long long)row * Dc + col] =
                    make_float2(acc[im][in_][0] + bv.x, acc[im][in_][1] + bv.y);
                *(float2*)&C[(long long)(row + 8) * Dc + col] =
                    make_float2(acc[im][in_][2] + bv.x, acc[im][in_][3] + bv.y);
            }
        }
    } else {
        // writer role: 4 rows per block, coalesced float4 streaming stores
        int wid_lin = ((blockIdx.z - 1) * gridDim.y + blockIdx.y) * gridDim.x + blockIdx.x;
        int j0 = threadIdx.x * 4;
        long long r0 = (long long)wid_lin * 4;
        float4 z4 = make_float4(0.f, 0.f, 0.f, 0.f);
#pragma unroll
        for (int rr = 0; rr < 4; rr++) {
            long long r = r0 + rr;
            int i = (int)(r & (Pc - 1));
            int k0w = ((i >> 6) << 6) - HALFW;
            float4 v = z4;
            if (j0 >= k0w && j0 < k0w + 128)
                v = *(const float4*)&Pwin[r * 128 + (j0 - k0w)];
            __stcs((float4*)&A1[r * Pc + j0], v);
        }
    }
}

// ---------------------------------------------------------------------------
// Tensor-core banded attention (round-11 structure); writes compact Pwin
// instead of dense A. 92.4KB smem -> 2 CTAs/SM.
// ---------------------------------------------------------------------------
#define AT_STRIDE 72
#define AS_STRIDE 132
#define AP_STRIDE 136
#define O_QH 0
#define O_QL 9216
#define O_KH 18432
#define O_KL 36864
#define O_PH 0
#define O_PL 17408
#define O_SS 55296
#define O_VH 55296
#define O_VL 73728
#define O_SINV 92160
#define ATTN_SMEM_BYTES 92416

__global__ __launch_bounds__(256, 2)
void attn_mma_kernel(const __nv_bfloat16* __restrict__ QKVhi,
                     const __nv_bfloat16* __restrict__ QKVlo,
                     __nv_bfloat16* __restrict__ Chi, __nv_bfloat16* __restrict__ Clo,
                     float* __restrict__ Pwin, int writeWin)
{
    extern __shared__ char smraw[];
    __nv_bfloat16* sQh = (__nv_bfloat16*)(smraw + O_QH);
    __nv_bfloat16* sQl = (__nv_bfloat16*)(smraw + O_QL);
    __nv_bfloat16* sKh = (__nv_bfloat16*)(smraw + O_KH);
    __nv_bfloat16* sKl = (__nv_bfloat16*)(smraw + O_KL);
    float*         sS  = (float*)(smraw + O_SS);
    __nv_bfloat16* sPh = (__nv_bfloat16*)(smraw + O_PH);
    __nv_bfloat16* sPl = (__nv_bfloat16*)(smraw + O_PL);
    __nv_bfloat16* sVh = (__nv_bfloat16*)(smraw + O_VH);
    __nv_bfloat16* sVl = (__nv_bfloat16*)(smraw + O_VL);
    float*         sinv = (float*)(smraw + O_SINV);
    unsigned smem_u32 = (unsigned)__cvta_generic_to_shared(smraw);

    int tid  = threadIdx.x;
    int lane = tid & 31;
    int warp = tid >> 5;
    int q0 = blockIdx.x * 64;
    int h  = blockIdx.y;
    int zz = blockIdx.z;
    int b  = zz >> 1;
    int which = zz & 1;
    int k0 = q0 - HALFW;
    const float scale = 0.125f;

    const long long plane = (long long)M_PROJ * Dc;
    const __nv_bfloat16 *Qh, *Ql, *Kh, *Kl, *Vh, *Vl;
    int rowOffset;
    if (which == 0) {
        Qh = QKVhi;           Ql = QKVlo;
        Kh = QKVhi + plane;   Kl = QKVlo + plane;
        Vh = QKVhi + 2*plane; Vl = QKVlo + 2*plane;
        rowOffset = 0;
    } else {
        Qh = QKVhi + plane;   Ql = QKVlo + plane;
        Kh = QKVhi;           Kl = QKVlo;
        Vh = QKVhi;           Vl = QKVlo;
        rowOffset = Pc;
    }
    long long headBase = (long long)b * Pc * Dc + (long long)h * DKc;
    const uint4 zero4 = make_uint4(0, 0, 0, 0);

    for (int t = tid; t < 512; t += 256) {
        int r = t >> 3, c = (t & 7) * 8;
        long long src = headBase + (long long)(q0 + r) * Dc + c;
        *(uint4*)&sQh[r * AT_STRIDE + c] = *(const uint4*)&Qh[src];
        *(uint4*)&sQl[r * AT_STRIDE + c] = *(const uint4*)&Ql[src];
    }
    for (int t = tid; t < 1024; t += 256) {
        int r = t >> 3, c = (t & 7) * 8;
        int j = k0 + r;
        uint4 kh = zero4, kl = zero4;
        if (j >= 0 && j < Pc) {
            long long src = headBase + (long long)j * Dc + c;
            kh = *(const uint4*)&Kh[src];
            kl = *(const uint4*)&Kl[src];
        }
        *(uint4*)&sKh[r * AT_STRIDE + c] = kh;
        *(uint4*)&sKl[r * AT_STRIDE + c] = kl;
    }
    __syncthreads();

    int m0 = (warp & 1) * 32;

    // ---- S = Q*K^T ----
    {
        int n0w = (warp >> 1) * 32;
        float sacc[2][4][4];
#pragma unroll
        for (int mi = 0; mi < 2; mi++)
#pragma unroll
            for (int ni = 0; ni < 4; ni++)
#pragma unroll
                for (int r = 0; r < 4; r++) sacc[mi][ni][r] = 0.f;

#pragma unroll
        for (int ks = 0; ks < 4; ks++) {
            int kc = ks * 16;
            unsigned ah[2][4], al[2][4];
#pragma unroll
            for (int mi = 0; mi < 2; mi++) {
                int row = m0 + mi * 16 + (lane & 15);
                int col = kc + 8 * (lane >> 4);
                unsigned off = (unsigned)(row * AT_STRIDE + col) * 2;
                ldmatrix_x4(ah[mi], smem_u32 + O_QH + off);
                ldmatrix_x4(al[mi], smem_u32 + O_QL + off);
            }
            unsigned bh[4][2], bl[4][2];
#pragma unroll
            for (int nt = 0; nt < 2; nt++) {
                int row = n0w + nt * 16 + (lane & 7) + 8 * (lane >> 4);
                int col = kc + 8 * ((lane >> 3) & 1);
                unsigned off = (unsigned)(row * AT_STRIDE + col) * 2;
                unsigned th[4], tl[4];
                ldmatrix_x4(th, smem_u32 + O_KH + off);
                ldmatrix_x4(tl, smem_u32 + O_KL + off);
                bh[2*nt][0] = th[0]; bh[2*nt][1] = th[1];
                bh[2*nt+1][0] = th[2]; bh[2*nt+1][1] = th[3];
                bl[2*nt][0] = tl[0]; bl[2*nt][1] = tl[1];
                bl[2*nt+1][0] = tl[2]; bl[2*nt+1][1] = tl[3];
            }
#pragma unroll
            for (int mi = 0; mi < 2; mi++)
#pragma unroll
                for (int ni = 0; ni < 4; ni++) {
                    mma_bf16(sacc[mi][ni], ah[mi], bh[ni]);
                    mma_bf16(sacc[mi][ni], ah[mi], bl[ni]);
                    mma_bf16(sacc[mi][ni], al[mi], bh[ni]);
                }
        }
#pragma unroll
        for (int mi = 0; mi < 2; mi++)
#pragma unroll
            for (int ni = 0; ni < 4; ni++) {
                int r = m0 + mi * 16 + (lane >> 2);
                int cc = n0w + ni * 8 + 2 * (lane & 3);
                *(float2*)&sS[r * AS_STRIDE + cc] =
                    make_float2(sacc[mi][ni][0], sacc[mi][ni][1]);
                *(float2*)&sS[(r + 8) * AS_STRIDE + cc] =
                    make_float2(sacc[mi][ni][2], sacc[mi][ni][3]);
            }
    }
    __syncthreads();   // Q/K reads done -> P may alias region1

    // ---- softmax ----
    {
        int qi = tid >> 2;
        int p  = tid & 3;
        int i_glob = q0 + qi;
        int jlo = i_glob - HALFW; if (jlo < 0) jlo = 0;
        int jhi = i_glob + HALFW; if (jhi > Pc - 1) jhi = Pc - 1;
        int kjlo = jlo - k0;
        int kjhi = jhi - k0;
        float* srow = &sS[qi * AS_STRIDE];
        float m = -1e30f;
#pragma unroll 8
        for (int t = 0; t < 32; t++) {
            int kj = p + 4 * t;
            if (kj >= kjlo && kj <= kjhi) m = fmaxf(m, srow[kj]);
        }
        m = fmaxf(m, __shfl_xor_sync(0xffffffffu, m, 1));
        m = fmaxf(m, __shfl_xor_sync(0xffffffffu, m, 2));
        float sum = 0.f;
#pragma unroll 8
        for (int t = 0; t < 32; t++) {
            int kj = p + 4 * t;
            float pv = 0.f;
            if (kj >= kjlo && kj <= kjhi) {
                pv = __expf(scale * (srow[kj] - m));
                sum += pv;
            }
            srow[kj] = pv;
            __nv_bfloat16 hh, ll;
            split_bf16(pv, hh, ll);
            sPh[qi * AP_STRIDE + kj] = hh;
            sPl[qi * AP_STRIDE + kj] = ll;
        }
        sum += __shfl_xor_sync(0xffffffffu, sum, 1);
        sum += __shfl_xor_sync(0xffffffffu, sum, 2);
        if (p == 0) sinv[qi] = 1.0f / sum;
    }
    __syncthreads();

    // ---- compact Pwin write: 64 rows x 128 cols, coalesced ----
    if (writeWin) {
        long long prBase = ((long long)which * Bc * Hc + (long long)b * Hc + h) * Pc + q0;
        for (int t = tid; t < 64 * 32; t += 256) {
            int row = t >> 5;
            int c4  = (t & 31) * 4;
            float inv = sinv[row];
            const float* srow = &sS[row * AS_STRIDE];
            float4 v = make_float4(srow[c4] * inv, srow[c4 + 1] * inv,
                                   srow[c4 + 2] * inv, srow[c4 + 3] * inv);
            __stcs((float4*)&Pwin[(prBase + row) * 128 + c4], v);
        }
    }
    __syncthreads();   // S reads done -> V may alias region2

    // ---- V load over dead S region ----
    for (int t = tid; t < 1024; t += 256) {
        int r = t >> 3, c = (t & 7) * 8;
        int j = k0 + r;
        uint4 vh = zero4, vl = zero4;
        if (j >= 0 && j < Pc) {
            long long src = headBase + (long long)j * Dc + c;
            vh = *(const uint4*)&Vh[src];
            vl = *(const uint4*)&Vl[src];
        }
        *(uint4*)&sVh[r * AT_STRIDE + c] = vh;
        *(uint4*)&sVl[r * AT_STRIDE + c] = vl;
    }
    __syncthreads();

    // ---- O = P*V ----
    {
        int n0o = (warp >> 1) * 16;
        float oacc[2][2][4];
#pragma unroll
        for (int mi = 0; mi < 2; mi++)
#pragma unroll
            for (int ni = 0; ni < 2; ni++)
#pragma unroll
                for (int r = 0; r < 4; r++) oacc[mi][ni][r] = 0.f;

#pragma unroll
        for (int ks = 0; ks < 8; ks++) {
            int kc = ks * 16;
            unsigned ah[2][4], al[2][4];
#pragma unroll
            for (int mi = 0; mi < 2; mi++) {
                int row = m0 + mi * 16 + (lane & 15);
                int col = kc + 8 * (lane >> 4);
                unsigned off = (unsigned)(row * AP_STRIDE + col) * 2;
                ldmatrix_x4(ah[mi], smem_u32 + O_PH + off);
                ldmatrix_x4(al[mi], smem_u32 + O_PL + off);
            }
            unsigned bh[2][2], bl[2][2];
            {
                int row = kc + (lane & 15);
                int col = n0o + 8 * (lane >> 4);
                unsigned off = (unsigned)(row * AT_STRIDE + col) * 2;
                unsigned th[4], tl[4];
                ldmatrix_x4_trans(th, smem_u32 + O_VH + off);
                ldmatrix_x4_trans(tl, smem_u32 + O_VL + off);
                bh[0][0] = th[0]; bh[0][1] = th[1];
                bh[1][0] = th[2]; bh[1][1] = th[3];
                bl[0][0] = tl[0]; bl[0][1] = tl[1];
                bl[1][0] = tl[2]; bl[1][1] = tl[3];
            }
#pragma unroll
            for (int mi = 0; mi < 2; mi++)
#pragma unroll
                for (int ni = 0; ni < 2; ni++) {
                    mma_bf16(oacc[mi][ni], ah[mi], bh[ni]);
                    mma_bf16(oacc[mi][ni], ah[mi], bl[ni]);
                    mma_bf16(oacc[mi][ni], al[mi], bh[ni]);
                }
        }

#pragma unroll
        for (int mi = 0; mi < 2; mi++)
#pragma unroll
            for (int ni = 0; ni < 2; ni++) {
                int qi0 = m0 + mi * 16 + (lane >> 2);
                int d   = n0o + ni * 8 + 2 * (lane & 3);
                float inv0 = sinv[qi0];
                float inv1 = sinv[qi0 + 8];
                float o0 = oacc[mi][ni][0] * inv0, o1 = oacc[mi][ni][1] * inv0;
                float o2 = oacc[mi][ni][2] * inv1, o3 = oacc[mi][ni][3] * inv1;
                long long dst0 = ((long long)b * CONCAT_P + rowOffset + q0 + qi0) * Dc
                                 + h * DKc + d;
                long long dst1 = dst0 + 8LL * Dc;
                __nv_bfloat16 h0, l0, h1, l1, h2, l2, h3, l3;
                split_bf16(o0, h0, l0); split_bf16(o1, h1, l1);
                split_bf16(o2, h2, l2); split_bf16(o3, h3, l3);
                *(__nv_bfloat162*)&Chi[dst0] = __nv_bfloat162(h0, h1);
                *(__nv_bfloat162*)&Clo[dst0] = __nv_bfloat162(l0, l1);
                *(__nv_bfloat162*)&Chi[dst1] = __nv_bfloat162(h2, h3);
                *(__nv_bfloat162*)&Clo[dst1] = __nv_bfloat162(l2, l3);
            }
    }
}

// ---------------------------------------------------------------------------
extern "C" void kernel_launch(void* const* d_in, const int* in_sizes, int n_in,
                              void* d_out, int out_size)
{
    const float* queries = (const float*)d_in[0];
    const float* keys    = (const float*)d_in[1];
    const float* values  = (const float*)d_in[2];
    const float* Wq = (const float*)d_in[3];
    const float* bq = (const float*)d_in[4];
    const float* Wk = (const float*)d_in[5];
    const float* bk = (const float*)d_in[6];
    const float* Wv = (const float*)d_in[7];
    const float* bv = (const float*)d_in[8];
    const float* Wo = (const float*)d_in[9];
    const float* bo = (const float*)d_in[10];

    float* out = (float*)d_out;

    __nv_bfloat16 *Ahi, *Alo, *Bhi, *Blo, *QKVhi, *QKVlo, *Chi, *Clo;
    float* Pwin;
    cudaGetSymbolAddress((void**)&Ahi, g_Ahi);
    cudaGetSymbolAddress((void**)&Alo, g_Alo);
    cudaGetSymbolAddress((void**)&Bhi, g_Bhi);
    cudaGetSymbolAddress((void**)&Blo, g_Blo);
    cudaGetSymbolAddress((void**)&QKVhi, g_QKVhi);
    cudaGetSymbolAddress((void**)&QKVlo, g_QKVlo);
    cudaGetSymbolAddress((void**)&Chi, g_Chi);
    cudaGetSymbolAddress((void**)&Clo, g_Clo);
    cudaGetSymbolAddress((void**)&Pwin, g_Pwin);

    static int attr_set = 0;
    if (!attr_set) {
        cudaFuncSetAttribute(attn_mma_kernel,
                             cudaFuncAttributeMaxDynamicSharedMemorySize, ATTN_SMEM_BYTES);
        cudaFuncSetAttribute(gemm_proj_kernel,
                             cudaFuncAttributeMaxDynamicSharedMemorySize, GEMM_SMEM_BYTES);
        cudaFuncSetAttribute(outgemm_writeA_kernel,
                             cudaFuncAttributeMaxDynamicSharedMemorySize, GEMM_SMEM_BYTES);
        attr_set = 1;
    }

    const long long mainN = (long long)M_OUT * Dc;
    const long long aN    = (long long)Bc * Hc * Pc * Pc;
    float* A1 = nullptr;
    bool hasA = ((long long)out_size >= mainN + 2 * aN);
    if (hasA) A1 = out + mainN;      // A2 contiguous after A1; writer covers both

    split_a_kernel<<<dim3(256, 1, 3), 256>>>(queries, keys, values, Ahi, Alo);
    split_b_kernel<<<dim3(16, 16, 4), dim3(32, 8)>>>(Wq, Wk, Wv, Wo, Bhi, Blo);

    const long long bStride = (long long)Dc * Dc;

    gemm_proj_kernel<<<dim3(Dc / 128, M_PROJ / 128, 3), 256, GEMM_SMEM_BYTES>>>(
        Ahi, Alo, Bhi, Blo, QKVhi, QKVlo, bq, bk, bv);

    dim3 ga(Pc / 64, Hc, Bc * 2);
    attn_mma_kernel<<<ga, 256, ATTN_SMEM_BYTES>>>(QKVhi, QKVlo, Chi, Clo,
                                                  Pwin, hasA ? 1 : 0);

    // fused: out-GEMM (z=0) + dense-A writer (z=1..64) run concurrently
    int Wz = hasA ? (NROWS / 4) / (4 * 64) : 0;    // 64
    dim3 go(Dc / 128, M_OUT / 128, 1 + Wz);
    outgemm_writeA_kernel<<<go, 256, GEMM_SMEM_BYTES>>>(
        Chi, Clo, Bhi + 3 * bStride, Blo + 3 * bStride, out, bo, Pwin, A1);
}

// round 15
// speedup vs baseline: 1.0549x; 1.0549x over previous
#include <cuda_runtime.h>
#include <cuda_bf16.h>
#include <math.h>

#define Bc   4
#define Pc   1024
#define Dc   512
#define Hc   8
#define DKc  64
#define HALFW 32
#define CONCAT_P (2*Pc)

#define M_PROJ (Bc * Pc)        // 4096
#define M_OUT  (Bc * CONCAT_P)  // 8192
#define NROWS (2 * Bc * Hc * Pc)   // 65536 dense-A rows (A1|A2)

__device__ __nv_bfloat16 g_Ahi[3 * M_PROJ * Dc];
__device__ __nv_bfloat16 g_Alo[3 * M_PROJ * Dc];
__device__ __nv_bfloat16 g_Bhi[4 * Dc * Dc];        // weights [n][k]
__device__ __nv_bfloat16 g_Blo[4 * Dc * Dc];
__device__ __nv_bfloat16 g_QKVhi[3 * M_PROJ * Dc];
__device__ __nv_bfloat16 g_QKVlo[3 * M_PROJ * Dc];
__device__ __nv_bfloat16 g_Chi[M_OUT * Dc];
__device__ __nv_bfloat16 g_Clo[M_OUT * Dc];
__device__ float g_Pwin[(long long)NROWS * 128];    // compact normalized windows

// ---------------------------------------------------------------------------
__device__ __forceinline__ void split_bf16(float v, __nv_bfloat16& hi, __nv_bfloat16& lo)
{
    hi = __float2bfloat16(v);
    lo = __float2bfloat16(v - __bfloat162float(hi));
}

__global__ void split_a_kernel(const float* __restrict__ s0, const float* __restrict__ s1,
                               const float* __restrict__ s2,
                               __nv_bfloat16* __restrict__ hi, __nv_bfloat16* __restrict__ lo)
{
    int z = blockIdx.z;
    const float* src = (z == 0) ? s0 : (z == 1) ? s1 : s2;
    long long base = (long long)z * M_PROJ * Dc;
    long long n4 = (long long)M_PROJ * Dc / 4;
    long long idx = (long long)blockIdx.x * blockDim.x + threadIdx.x;
    long long stride = (long long)gridDim.x * blockDim.x;
    for (long long i = idx; i < n4; i += stride) {
        float4 v = ((const float4*)src)[i];
        __nv_bfloat16 h[4], l[4];
        split_bf16(v.x, h[0], l[0]);
        split_bf16(v.y, h[1], l[1]);
        split_bf16(v.z, h[2], l[2]);
        split_bf16(v.w, h[3], l[3]);
        long long o = base + i * 4;
        *(__nv_bfloat162*)&hi[o]     = __nv_bfloat162(h[0], h[1]);
        *(__nv_bfloat162*)&hi[o + 2] = __nv_bfloat162(h[2], h[3]);
        *(__nv_bfloat162*)&lo[o]     = __nv_bfloat162(l[0], l[1]);
        *(__nv_bfloat162*)&lo[o + 2] = __nv_bfloat162(l[2], l[3]);
    }
}

__global__ void split_b_kernel(const float* __restrict__ w0, const float* __restrict__ w1,
                               const float* __restrict__ w2, const float* __restrict__ w3,
                               __nv_bfloat16* __restrict__ hi, __nv_bfloat16* __restrict__ lo)
{
    __shared__ float t[32][33];
    int z = blockIdx.z;
    const float* W = (z == 0) ? w0 : (z == 1) ? w1 : (z == 2) ? w2 : w3;
    long long base = (long long)z * Dc * Dc;
    int n0 = blockIdx.x * 32;
    int k0 = blockIdx.y * 32;
    int tx = threadIdx.x, ty = threadIdx.y;
#pragma unroll
    for (int i = 0; i < 4; i++)
        t[ty + i * 8][tx] = W[(long long)(k0 + ty + i * 8) * Dc + n0 + tx];
    __syncthreads();
#pragma unroll
    for (int i = 0; i < 4; i++) {
        float v = t[tx][ty + i * 8];
        long long o = base + (long long)(n0 + ty + i * 8) * Dc + k0 + tx;
        __nv_bfloat16 h, l;
        split_bf16(v, h, l);
        hi[o] = h;
        lo[o] = l;
    }
}

// ---------------------------------------------------------------------------
// mma / ldmatrix helpers
// ---------------------------------------------------------------------------
__device__ __forceinline__ void mma_bf16(float* d, const unsigned* a, const unsigned* b)
{
    asm volatile(
        "mma.sync.aligned.m16n8k16.row.col.f32.bf16.bf16.f32 "
        "{%0,%1,%2,%3}, {%4,%5,%6,%7}, {%8,%9}, {%0,%1,%2,%3};"
        : "+f"(d[0]), "+f"(d[1]), "+f"(d[2]), "+f"(d[3])
        : "r"(a[0]), "r"(a[1]), "r"(a[2]), "r"(a[3]), "r"(b[0]), "r"(b[1]));
}

__device__ __forceinline__ void ldmatrix_x4(unsigned* r, unsigned addr)
{
    asm volatile("ldmatrix.sync.aligned.m8n8.x4.shared.b16 {%0,%1,%2,%3}, [%4];"
        : "=r"(r[0]), "=r"(r[1]), "=r"(r[2]), "=r"(r[3]) : "r"(addr));
}

__device__ __forceinline__ void ldmatrix_x4_trans(unsigned* r, unsigned addr)
{
    asm volatile("ldmatrix.sync.aligned.m8n8.x4.trans.shared.b16 {%0,%1,%2,%3}, [%4];"
        : "=r"(r[0]), "=r"(r[1]), "=r"(r[2]), "=r"(r[3]) : "r"(addr));
}

__device__ __forceinline__ void cpasync16(void* dst_sh, const void* src)
{
    unsigned sh = (unsigned)__cvta_generic_to_shared(dst_sh);
    asm volatile("cp.async.cg.shared.global [%0], [%1], 16;\n" :: "r"(sh), "l"(src));
}

// ---------------------------------------------------------------------------
// Shared GEMM mainloop body (bf16-split, ldmatrix fragments).
// ---------------------------------------------------------------------------
#define GS_STRIDE 40
#define GS_TILE   (128 * GS_STRIDE)
#define GS_STAGE  (4 * GS_TILE)
#define GEMM_SMEM_BYTES (2 * GS_STAGE * 2)   // 81920

__device__ __forceinline__
void gemm_mainloop(const __nv_bfloat16* Ah, const __nv_bfloat16* Al,
                   const __nv_bfloat16* Bh, const __nv_bfloat16* Bl,
                   __nv_bfloat16* smem, unsigned smem_u32,
                   int row0, int col0, float acc[4][4][4])
{
    int tid  = threadIdx.x;
    int lane = tid & 31;
    int warp = tid >> 5;
    int wm = (warp & 1) * 64;
    int wn = (warp >> 1) * 32;

    int cp_arr[8], cp_row[8], cp_c[8];
#pragma unroll
    for (int i = 0; i < 8; i++) {
        cp_arr[i] = i >> 1;
        int idx2 = ((i & 1) << 8) + tid;
        cp_row[i] = idx2 >> 2;
        cp_c[i] = (idx2 & 3) * 8;
    }

    const int nIt = Dc / 32;

    auto load_stage = [&](int it, int s) {
        __nv_bfloat16* st = smem + s * GS_STAGE;
        int k0 = it * 32;
#pragma unroll
        for (int i = 0; i < 8; i++) {
            const __nv_bfloat16* src;
            int row = cp_row[i];
            int c = cp_c[i];
            if (cp_arr[i] == 0)      src = Ah + (long long)(row0 + row) * Dc + k0 + c;
            else if (cp_arr[i] == 1) src = Al + (long long)(row0 + row) * Dc + k0 + c;
            else if (cp_arr[i] == 2) src = Bh + (long long)(col0 + row) * Dc + k0 + c;
            else                     src = Bl + (long long)(col0 + row) * Dc + k0 + c;
            cpasync16(st + cp_arr[i] * GS_TILE + row * GS_STRIDE + c, src);
        }
        asm volatile("cp.async.commit_group;\n" ::);
    };

    load_stage(0, 0);

    for (int it = 0; it < nIt; it++) {
        int buf = it & 1;
        if (it + 1 < nIt) {
            load_stage(it + 1, buf ^ 1);
            asm volatile("cp.async.wait_group 1;\n" ::);
        } else {
            asm volatile("cp.async.wait_group 0;\n" ::);
        }
        __syncthreads();

        unsigned stage_base = smem_u32 + (unsigned)(buf * GS_STAGE * 2);
        unsigned uAh = stage_base;
        unsigned uAl = stage_base + GS_TILE * 2;
        unsigned uBh = stage_base + 2 * GS_TILE * 2;
        unsigned uBl = stage_base + 3 * GS_TILE * 2;

#pragma unroll
        for (int kk = 0; kk < 32; kk += 16) {
            unsigned a_h[4][4], a_l[4][4];
#pragma unroll
            for (int im = 0; im < 4; im++) {
                int row = wm + im * 16 + (lane & 15);
                int col = kk + 8 * (lane >> 4);
                unsigned off = (unsigned)(row * GS_STRIDE + col) * 2;
                ldmatrix_x4(a_h[im], uAh + off);
                ldmatrix_x4(a_l[im], uAl + off);
            }
            unsigned b_h[4][2], b_l[4][2];
#pragma unroll
            for (int nt = 0; nt < 2; nt++) {
                int row = wn + nt * 16 + (lane & 7) + 8 * (lane >> 4);
                int col = kk + 8 * ((lane >> 3) & 1);
                unsigned off = (unsigned)(row * GS_STRIDE + col) * 2;
                unsigned th[4], tl[4];
                ldmatrix_x4(th, uBh + off);
                ldmatrix_x4(tl, uBl + off);
                b_h[2*nt][0] = th[0];   b_h[2*nt][1] = th[1];
                b_h[2*nt+1][0] = th[2]; b_h[2*nt+1][1] = th[3];
                b_l[2*nt][0] = tl[0];   b_l[2*nt][1] = tl[1];
                b_l[2*nt+1][0] = tl[2]; b_l[2*nt+1][1] = tl[3];
            }
#pragma unroll
            for (int im = 0; im < 4; im++)
#pragma unroll
                for (int in_ = 0; in_ < 4; in_++) {
                    mma_bf16(acc[im][in_], a_h[im], b_h[in_]);
                    mma_bf16(acc[im][in_], a_h[im], b_l[in_]);
                    mma_bf16(acc[im][in_], a_l[im], b_h[in_]);
                }
        }
        __syncthreads();
    }
}

// ---------------------------------------------------------------------------
// Projection GEMM: 3 z-slices, epilogue writes bf16 hi/lo QKV
// ---------------------------------------------------------------------------
__global__ __launch_bounds__(256)
void gemm_proj_kernel(const __nv_bfloat16* __restrict__ Ah, const __nv_bfloat16* __restrict__ Al,
                      const __nv_bfloat16* __restrict__ Bh, const __nv_bfloat16* __restrict__ Bl,
                      __nv_bfloat16* Chi, __nv_bfloat16* Clo,
                      const float* b0, const float* b1, const float* b2)
{
    extern __shared__ __nv_bfloat16 smem[];
    unsigned smem_u32 = (unsigned)__cvta_generic_to_shared(smem);
    int z = blockIdx.z;
    const long long aStride = (long long)M_PROJ * Dc;
    const long long bStride = (long long)Dc * Dc;
    Ah += z * aStride; Al += z * aStride;
    Bh += z * bStride; Bl += z * bStride;
    const float* bias = (z == 0) ? b0 : (z == 1) ? b1 : b2;

    int lane = threadIdx.x & 31;
    int warp = threadIdx.x >> 5;
    int wm = (warp & 1) * 64;
    int wn = (warp >> 1) * 32;
    int row0 = blockIdx.y * 128;
    int col0 = blockIdx.x * 128;

    float acc[4][4][4];
#pragma unroll
    for (int im = 0; im < 4; im++)
#pragma unroll
        for (int in_ = 0; in_ < 4; in_++)
#pragma unroll
            for (int r = 0; r < 4; r++) acc[im][in_][r] = 0.f;

    gemm_mainloop(Ah, Al, Bh, Bl, smem, smem_u32, row0, col0, acc);

    long long cb = (long long)z * aStride;
#pragma unroll
    for (int im = 0; im < 4; im++) {
#pragma unroll
        for (int in_ = 0; in_ < 4; in_++) {
            int row = row0 + wm + im * 16 + (lane >> 2);
            int col = col0 + wn + in_ * 8 + 2 * (lane & 3);
            float2 bv = *(const float2*)&bias[col];
            float o0 = acc[im][in_][0] + bv.x, o1 = acc[im][in_][1] + bv.y;
            float o2 = acc[im][in_][2] + bv.x, o3 = acc[im][in_][3] + bv.y;
            __nv_bfloat16 h0, l0, h1, l1, h2, l2, h3, l3;
            split_bf16(o0, h0, l0); split_bf16(o1, h1, l1);
            split_bf16(o2, h2, l2); split_bf16(o3, h3, l3);
            *(__nv_bfloat162*)&Chi[cb + (long long)row * Dc + col]       = __nv_bfloat162(h0, h1);
            *(__nv_bfloat162*)&Clo[cb + (long long)row * Dc + col]       = __nv_bfloat162(l0, l1);
            *(__nv_bfloat162*)&Chi[cb + (long long)(row + 8) * Dc + col] = __nv_bfloat162(h2, h3);
            *(__nv_bfloat162*)&Clo[cb + (long long)(row + 8) * Dc + col] = __nv_bfloat162(l2, l3);
        }
    }
}

// ---------------------------------------------------------------------------
// Fused out-GEMM + dense-A writer, roles interleaved in schedule order.
// hasA: grid (4, 128) — even y = GEMM tile (y>>1), odd y = writer block.
// !hasA: grid (4, 64) — all GEMM.
// Writer: 256 blocks, each streams 256 full rows (4KB, coalesced) from Pwin.
// ---------------------------------------------------------------------------
__global__ __launch_bounds__(256)
void outgemm_writeA_kernel(const __nv_bfloat16* __restrict__ Ah, const __nv_bfloat16* __restrict__ Al,
                           const __nv_bfloat16* __restrict__ Bh, const __nv_bfloat16* __restrict__ Bl,
                           float* __restrict__ C, const float* __restrict__ bias,
                           const float* __restrict__ Pwin, float* __restrict__ A1,
                           int interleaved)
{
    extern __shared__ __nv_bfloat16 smem[];
    bool isWriter = interleaved && (blockIdx.y & 1);
    if (!isWriter) {
        unsigned smem_u32 = (unsigned)__cvta_generic_to_shared(smem);
        int lane = threadIdx.x & 31;
        int warp = threadIdx.x >> 5;
        int wm = (warp & 1) * 64;
        int wn = (warp >> 1) * 32;
        int ytile = interleaved ? (blockIdx.y >> 1) : blockIdx.y;
        int row0 = ytile * 128;
        int col0 = blockIdx.x * 128;

        float acc[4][4][4];
#pragma unroll
        for (int im = 0; im < 4; im++)
#pragma unroll
            for (int in_ = 0; in_ < 4; in_++)
#pragma unroll
                for (int r = 0; r < 4; r++) acc[im][in_][r] = 0.f;

        gemm_mainloop(Ah, Al, Bh, Bl, smem, smem_u32, row0, col0, acc);

#pragma unroll
        for (int im = 0; im < 4; im++) {
#pragma unroll
            for (int in_ = 0; in_ < 4; in_++) {
                int row = row0 + wm + im * 16 + (lane >> 2);
                int col = col0 + wn + in_ * 8 + 2 * (lane & 3);
                float2 bv = *(const float2*)&bias[col];
                *(float2*)&C[(long long)row * Dc + col] =
                    make_float2(acc[im][in_][0] + bv.x, acc[im][in_][1] + bv.y);
                *(float2*)&C[(long long)(row + 8) * Dc + col] =
                    make_float2(acc[im][in_][2] + bv.x, acc[im][in_][3] + bv.y);
            }
        }
    } else {
        // writer role: 256 blocks, each 256 rows; one 4KB row per iteration.
        int wid_lin = (blockIdx.y >> 1) * gridDim.x + blockIdx.x;   // 0..255
        int j0 = threadIdx.x * 4;
        const int nBlocksW = 256;
        float4 z4 = make_float4(0.f, 0.f, 0.f, 0.f);
#pragma unroll 4
        for (int it = 0; it < NROWS / nBlocksW; it++) {
            long long r = (long long)wid_lin + (long long)it * nBlocksW;
            int i = (int)(r & (Pc - 1));
            int k0w = ((i >> 6) << 6) - HALFW;
            float4 v = z4;
            if (j0 >= k0w && j0 < k0w + 128)
                v = *(const float4*)&Pwin[r * 128 + (j0 - k0w)];
            __stcs((float4*)&A1[r * Pc + j0], v);
        }
    }
}

// ---------------------------------------------------------------------------
// Tensor-core banded attention (unchanged from round 14; writes compact Pwin).
// ---------------------------------------------------------------------------
#define AT_STRIDE 72
#define AS_STRIDE 132
#define AP_STRIDE 136
#define O_QH 0
#define O_QL 9216
#define O_KH 18432
#define O_KL 36864
#define O_PH 0
#define O_PL 17408
#define O_SS 55296
#define O_VH 55296
#define O_VL 73728
#define O_SINV 92160
#define ATTN_SMEM_BYTES 92416

__global__ __launch_bounds__(256, 2)
void attn_mma_kernel(const __nv_bfloat16* __restrict__ QKVhi,
                     const __nv_bfloat16* __restrict__ QKVlo,
                     __nv_bfloat16* __restrict__ Chi, __nv_bfloat16* __restrict__ Clo,
                     float* __restrict__ Pwin, int writeWin)
{
    extern __shared__ char smraw[];
    __nv_bfloat16* sQh = (__nv_bfloat16*)(smraw + O_QH);
    __nv_bfloat16* sQl = (__nv_bfloat16*)(smraw + O_QL);
    __nv_bfloat16* sKh = (__nv_bfloat16*)(smraw + O_KH);
    __nv_bfloat16* sKl = (__nv_bfloat16*)(smraw + O_KL);
    float*         sS  = (float*)(smraw + O_SS);
    __nv_bfloat16* sPh = (__nv_bfloat16*)(smraw + O_PH);
    __nv_bfloat16* sPl = (__nv_bfloat16*)(smraw + O_PL);
    __nv_bfloat16* sVh = (__nv_bfloat16*)(smraw + O_VH);
    __nv_bfloat16* sVl = (__nv_bfloat16*)(smraw + O_VL);
    float*         sinv = (float*)(smraw + O_SINV);
    unsigned smem_u32 = (unsigned)__cvta_generic_to_shared(smraw);

    int tid  = threadIdx.x;
    int lane = tid & 31;
    int warp = tid >> 5;
    int q0 = blockIdx.x * 64;
    int h  = blockIdx.y;
    int zz = blockIdx.z;
    int b  = zz >> 1;
    int which = zz & 1;
    int k0 = q0 - HALFW;
    const float scale = 0.125f;

    const long long plane = (long long)M_PROJ * Dc;
    const __nv_bfloat16 *Qh, *Ql, *Kh, *Kl, *Vh, *Vl;
    int rowOffset;
    if (which == 0) {
        Qh = QKVhi;           Ql = QKVlo;
        Kh = QKVhi + plane;   Kl = QKVlo + plane;
        Vh = QKVhi + 2*plane; Vl = QKVlo + 2*plane;
        rowOffset = 0;
    } else {
        Qh = QKVhi + plane;   Ql = QKVlo + plane;
        Kh = QKVhi;           Kl = QKVlo;
        Vh = QKVhi;           Vl = QKVlo;
        rowOffset = Pc;
    }
    long long headBase = (long long)b * Pc * Dc + (long long)h * DKc;
    const uint4 zero4 = make_uint4(0, 0, 0, 0);

    for (int t = tid; t < 512; t += 256) {
        int r = t >> 3, c = (t & 7) * 8;
        long long src = headBase + (long long)(q0 + r) * Dc + c;
        *(uint4*)&sQh[r * AT_STRIDE + c] = *(const uint4*)&Qh[src];
        *(uint4*)&sQl[r * AT_STRIDE + c] = *(const uint4*)&Ql[src];
    }
    for (int t = tid; t < 1024; t += 256) {
        int r = t >> 3, c = (t & 7) * 8;
        int j = k0 + r;
        uint4 kh = zero4, kl = zero4;
        if (j >= 0 && j < Pc) {
            long long src = headBase + (long long)j * Dc + c;
            kh = *(const uint4*)&Kh[src];
            kl = *(const uint4*)&Kl[src];
        }
        *(uint4*)&sKh[r * AT_STRIDE + c] = kh;
        *(uint4*)&sKl[r * AT_STRIDE + c] = kl;
    }
    __syncthreads();

    int m0 = (warp & 1) * 32;

    // ---- S = Q*K^T ----
    {
        int n0w = (warp >> 1) * 32;
        float sacc[2][4][4];
#pragma unroll
        for (int mi = 0; mi < 2; mi++)
#pragma unroll
            for (int ni = 0; ni < 4; ni++)
#pragma unroll
                for (int r = 0; r < 4; r++) sacc[mi][ni][r] = 0.f;

#pragma unroll
        for (int ks = 0; ks < 4; ks++) {
            int kc = ks * 16;
            unsigned ah[2][4], al[2][4];
#pragma unroll
            for (int mi = 0; mi < 2; mi++) {
                int row = m0 + mi * 16 + (lane & 15);
                int col = kc + 8 * (lane >> 4);
                unsigned off = (unsigned)(row * AT_STRIDE + col) * 2;
                ldmatrix_x4(ah[mi], smem_u32 + O_QH + off);
                ldmatrix_x4(al[mi], smem_u32 + O_QL + off);
            }
            unsigned bh[4][2], bl[4][2];
#pragma unroll
            for (int nt = 0; nt < 2; nt++) {
                int row = n0w + nt * 16 + (lane & 7) + 8 * (lane >> 4);
                int col = kc + 8 * ((lane >> 3) & 1);
                unsigned off = (unsigned)(row * AT_STRIDE + col) * 2;
                unsigned th[4], tl[4];
                ldmatrix_x4(th, smem_u32 + O_KH + off);
                ldmatrix_x4(tl, smem_u32 + O_KL + off);
                bh[2*nt][0] = th[0]; bh[2*nt][1] = th[1];
                bh[2*nt+1][0] = th[2]; bh[2*nt+1][1] = th[3];
                bl[2*nt][0] = tl[0]; bl[2*nt][1] = tl[1];
                bl[2*nt+1][0] = tl[2]; bl[2*nt+1][1] = tl[3];
            }
#pragma unroll
            for (int mi = 0; mi < 2; mi++)
#pragma unroll
                for (int ni = 0; ni < 4; ni++) {
                    mma_bf16(sacc[mi][ni], ah[mi], bh[ni]);
                    mma_bf16(sacc[mi][ni], ah[mi], bl[ni]);
                    mma_bf16(sacc[mi][ni], al[mi], bh[ni]);
                }
        }
#pragma unroll
        for (int mi = 0; mi < 2; mi++)
#pragma unroll
            for (int ni = 0; ni < 4; ni++) {
                int r = m0 + mi * 16 + (lane >> 2);
                int cc = n0w + ni * 8 + 2 * (lane & 3);
                *(float2*)&sS[r * AS_STRIDE + cc] =
                    make_float2(sacc[mi][ni][0], sacc[mi][ni][1]);
                *(float2*)&sS[(r + 8) * AS_STRIDE + cc] =
                    make_float2(sacc[mi][ni][2], sacc[mi][ni][3]);
            }
    }
    __syncthreads();

    // ---- softmax ----
    {
        int qi = tid >> 2;
        int p  = tid & 3;
        int i_glob = q0 + qi;
        int jlo = i_glob - HALFW; if (jlo < 0) jlo = 0;
        int jhi = i_glob + HALFW; if (jhi > Pc - 1) jhi = Pc - 1;
        int kjlo = jlo - k0;
        int kjhi = jhi - k0;
        float* srow = &sS[qi * AS_STRIDE];
        float m = -1e30f;
#pragma unroll 8
        for (int t = 0; t < 32; t++) {
            int kj = p + 4 * t;
            if (kj >= kjlo && kj <= kjhi) m = fmaxf(m, srow[kj]);
        }
        m = fmaxf(m, __shfl_xor_sync(0xffffffffu, m, 1));
        m = fmaxf(m, __shfl_xor_sync(0xffffffffu, m, 2));
        float sum = 0.f;
#pragma unroll 8
        for (int t = 0; t < 32; t++) {
            int kj = p + 4 * t;
            float pv = 0.f;
            if (kj >= kjlo && kj <= kjhi) {
                pv = __expf(scale * (srow[kj] - m));
                sum += pv;
            }
            srow[kj] = pv;
            __nv_bfloat16 hh, ll;
            split_bf16(pv, hh, ll);
            sPh[qi * AP_STRIDE + kj] = hh;
            sPl[qi * AP_STRIDE + kj] = ll;
        }
        sum += __shfl_xor_sync(0xffffffffu, sum, 1);
        sum += __shfl_xor_sync(0xffffffffu, sum, 2);
        if (p == 0) sinv[qi] = 1.0f / sum;
    }
    __syncthreads();

    // ---- compact Pwin write ----
    if (writeWin) {
        long long prBase = ((long long)which * Bc * Hc + (long long)b * Hc + h) * Pc + q0;
        for (int t = tid; t < 64 * 32; t += 256) {
            int row = t >> 5;
            int c4  = (t & 31) * 4;
            float inv = sinv[row];
            const float* srow = &sS[row * AS_STRIDE];
            float4 v = make_float4(srow[c4] * inv, srow[c4 + 1] * inv,
                                   srow[c4 + 2] * inv, srow[c4 + 3] * inv);
            __stcs((float4*)&Pwin[(prBase + row) * 128 + c4], v);
        }
    }
    __syncthreads();

    // ---- V load over dead S region ----
    for (int t = tid; t < 1024; t += 256) {
        int r = t >> 3, c = (t & 7) * 8;
        int j = k0 + r;
        uint4 vh = zero4, vl = zero4;
        if (j >= 0 && j < Pc) {
            long long src = headBase + (long long)j * Dc + c;
            vh = *(const uint4*)&Vh[src];
            vl = *(const uint4*)&Vl[src];
        }
        *(uint4*)&sVh[r * AT_STRIDE + c] = vh;
        *(uint4*)&sVl[r * AT_STRIDE + c] = vl;
    }
    __syncthreads();

    // ---- O = P*V ----
    {
        int n0o = (warp >> 1) * 16;
        float oacc[2][2][4];
#pragma unroll
        for (int mi = 0; mi < 2; mi++)
#pragma unroll
            for (int ni = 0; ni < 2; ni++)
#pragma unroll
                for (int r = 0; r < 4; r++) oacc[mi][ni][r] = 0.f;

#pragma unroll
        for (int ks = 0; ks < 8; ks++) {
            int kc = ks * 16;
            unsigned ah[2][4], al[2][4];
#pragma unroll
            for (int mi = 0; mi < 2; mi++) {
                int row = m0 + mi * 16 + (lane & 15);
                int col = kc + 8 * (lane >> 4);
                unsigned off = (unsigned)(row * AP_STRIDE + col) * 2;
                ldmatrix_x4(ah[mi], smem_u32 + O_PH + off);
                ldmatrix_x4(al[mi], smem_u32 + O_PL + off);
            }
            unsigned bh[2][2], bl[2][2];
            {
                int row = kc + (lane & 15);
                int col = n0o + 8 * (lane >> 4);
                unsigned off = (unsigned)(row * AT_STRIDE + col) * 2;
                unsigned th[4], tl[4];
                ldmatrix_x4_trans(th, smem_u32 + O_VH + off);
                ldmatrix_x4_trans(tl, smem_u32 + O_VL + off);
                bh[0][0] = th[0]; bh[0][1] = th[1];
                bh[1][0] = th[2]; bh[1][1] = th[3];
                bl[0][0] = tl[0]; bl[0][1] = tl[1];
                bl[1][0] = tl[2]; bl[1][1] = tl[3];
            }
#pragma unroll
            for (int mi = 0; mi < 2; mi++)
#pragma unroll
                for (int ni = 0; ni < 2; ni++) {
                    mma_bf16(oacc[mi][ni], ah[mi], bh[ni]);
                    mma_bf16(oacc[mi][ni], ah[mi], bl[ni]);
                    mma_bf16(oacc[mi][ni], al[mi], bh[ni]);
                }
        }

#pragma unroll
        for (int mi = 0; mi < 2; mi++)
#pragma unroll
            for (int ni = 0; ni < 2; ni++) {
                int qi0 = m0 + mi * 16 + (lane >> 2);
                int d   = n0o + ni * 8 + 2 * (lane & 3);
                float inv0 = sinv[qi0];
                float inv1 = sinv[qi0 + 8];
                float o0 = oacc[mi][ni][0] * inv0, o1 = oacc[mi][ni][1] * inv0;
                float o2 = oacc[mi][ni][2] * inv1, o3 = oacc[mi][ni][3] * inv1;
                long long dst0 = ((long long)b * CONCAT_P + rowOffset + q0 + qi0) * Dc
                                 + h * DKc + d;
                long long dst1 = dst0 + 8LL * Dc;
                __nv_bfloat16 h0, l0, h1, l1, h2, l2, h3, l3;
                split_bf16(o0, h0, l0); split_bf16(o1, h1, l1);
                split_bf16(o2, h2, l2); split_bf16(o3, h3, l3);
                *(__nv_bfloat162*)&Chi[dst0] = __nv_bfloat162(h0, h1);
                *(__nv_bfloat162*)&Clo[dst0] = __nv_bfloat162(l0, l1);
                *(__nv_bfloat162*)&Chi[dst1] = __nv_bfloat162(h2, h3);
                *(__nv_bfloat162*)&Clo[dst1] = __nv_bfloat162(l2, l3);
            }
    }
}

// ---------------------------------------------------------------------------
extern "C" void kernel_launch(void* const* d_in, const int* in_sizes, int n_in,
                              void* d_out, int out_size)
{
    const float* queries = (const float*)d_in[0];
    const float* keys    = (const float*)d_in[1];
    const float* values  = (const float*)d_in[2];
    const float* Wq = (const float*)d_in[3];
    const float* bq = (const float*)d_in[4];
    const float* Wk = (const float*)d_in[5];
    const float* bk = (const float*)d_in[6];
    const float* Wv = (const float*)d_in[7];
    const float* bv = (const float*)d_in[8];
    const float* Wo = (const float*)d_in[9];
    const float* bo = (const float*)d_in[10];

    float* out = (float*)d_out;

    __nv_bfloat16 *Ahi, *Alo, *Bhi, *Blo, *QKVhi, *QKVlo, *Chi, *Clo;
    float* Pwin;
    cudaGetSymbolAddress((void**)&Ahi, g_Ahi);
    cudaGetSymbolAddress((void**)&Alo, g_Alo);
    cudaGetSymbolAddress((void**)&Bhi, g_Bhi);
    cudaGetSymbolAddress((void**)&Blo, g_Blo);
    cudaGetSymbolAddress((void**)&QKVhi, g_QKVhi);
    cudaGetSymbolAddress((void**)&QKVlo, g_QKVlo);
    cudaGetSymbolAddress((void**)&Chi, g_Chi);
    cudaGetSymbolAddress((void**)&Clo, g_Clo);
    cudaGetSymbolAddress((void**)&Pwin, g_Pwin);

    static int attr_set = 0;
    if (!attr_set) {
        cudaFuncSetAttribute(attn_mma_kernel,
                             cudaFuncAttributeMaxDynamicSharedMemorySize, ATTN_SMEM_BYTES);
        cudaFuncSetAttribute(gemm_proj_kernel,
                             cudaFuncAttributeMaxDynamicSharedMemorySize, GEMM_SMEM_BYTES);
        cudaFuncSetAttribute(outgemm_writeA_kernel,
                             cudaFuncAttributeMaxDynamicSharedMemorySize, GEMM_SMEM_BYTES);
        attr_set = 1;
    }

    const long long mainN = (long long)M_OUT * Dc;
    const long long aN    = (long long)Bc * Hc * Pc * Pc;
    float* A1 = nullptr;
    bool hasA = ((long long)out_size >= mainN + 2 * aN);
    if (hasA) A1 = out + mainN;      // A2 contiguous after A1; writer covers both

    split_a_kernel<<<dim3(256, 1, 3), 256>>>(queries, keys, values, Ahi, Alo);
    split_b_kernel<<<dim3(16, 16, 4), dim3(32, 8)>>>(Wq, Wk, Wv, Wo, Bhi, Blo);

    const long long bStride = (long long)Dc * Dc;

    gemm_proj_kernel<<<dim3(Dc / 128, M_PROJ / 128, 3), 256, GEMM_SMEM_BYTES>>>(
        Ahi, Alo, Bhi, Blo, QKVhi, QKVlo, bq, bk, bv);

    dim3 ga(Pc / 64, Hc, Bc * 2);
    attn_mma_kernel<<<ga, 256, ATTN_SMEM_BYTES>>>(QKVhi, QKVlo, Chi, Clo,
                                                  Pwin, hasA ? 1 : 0);

    // fused: out-GEMM + dense-A writer, interleaved roles (even/odd y)
    dim3 go(Dc / 128, hasA ? (2 * M_OUT / 128) : (M_OUT / 128), 1);
    outgemm_writeA_kernel<<<go, 256, GEMM_SMEM_BYTES>>>(
        Chi, Clo, Bhi + 3 * bStride, Blo + 3 * bStride, out, bo, Pwin, A1,
        hasA ? 1 : 0);
}

// round 16
// speedup vs baseline: 1.2470x; 1.1821x over previous
#include <cuda_runtime.h>
#include <cuda_bf16.h>
#include <math.h>

#define Bc   4
#define Pc   1024
#define Dc   512
#define Hc   8
#define DKc  64
#define HALFW 32
#define CONCAT_P (2*Pc)

#define M_PROJ (Bc * Pc)        // 4096
#define M_OUT  (Bc * CONCAT_P)  // 8192
#define NROWS (2 * Bc * Hc * Pc)   // 65536 dense-A rows (A1|A2)

__device__ __nv_bfloat16 g_Ahi[3 * M_PROJ * Dc];
__device__ __nv_bfloat16 g_Alo[3 * M_PROJ * Dc];
__device__ __nv_bfloat16 g_Bhi[4 * Dc * Dc];        // weights [n][k]
__device__ __nv_bfloat16 g_Blo[4 * Dc * Dc];
__device__ __nv_bfloat16 g_QKVhi[3 * M_PROJ * Dc];
__device__ __nv_bfloat16 g_QKVlo[3 * M_PROJ * Dc];
__device__ __nv_bfloat16 g_Chi[M_OUT * Dc];
__device__ __nv_bfloat16 g_Clo[M_OUT * Dc];
__device__ float g_Pwin[(long long)NROWS * 128];    // compact normalized windows

// ---------------------------------------------------------------------------
__device__ __forceinline__ void split_bf16(float v, __nv_bfloat16& hi, __nv_bfloat16& lo)
{
    hi = __float2bfloat16(v);
    lo = __float2bfloat16(v - __bfloat162float(hi));
}

__global__ void split_a_kernel(const float* __restrict__ s0, const float* __restrict__ s1,
                               const float* __restrict__ s2,
                               __nv_bfloat16* __restrict__ hi, __nv_bfloat16* __restrict__ lo)
{
    int z = blockIdx.z;
    const float* src = (z == 0) ? s0 : (z == 1) ? s1 : s2;
    long long base = (long long)z * M_PROJ * Dc;
    long long n4 = (long long)M_PROJ * Dc / 4;
    long long idx = (long long)blockIdx.x * blockDim.x + threadIdx.x;
    long long stride = (long long)gridDim.x * blockDim.x;
    for (long long i = idx; i < n4; i += stride) {
        float4 v = ((const float4*)src)[i];
        __nv_bfloat16 h[4], l[4];
        split_bf16(v.x, h[0], l[0]);
        split_bf16(v.y, h[1], l[1]);
        split_bf16(v.z, h[2], l[2]);
        split_bf16(v.w, h[3], l[3]);
        long long o = base + i * 4;
        *(__nv_bfloat162*)&hi[o]     = __nv_bfloat162(h[0], h[1]);
        *(__nv_bfloat162*)&hi[o + 2] = __nv_bfloat162(h[2], h[3]);
        *(__nv_bfloat162*)&lo[o]     = __nv_bfloat162(l[0], l[1]);
        *(__nv_bfloat162*)&lo[o + 2] = __nv_bfloat162(l[2], l[3]);
    }
}

__global__ void split_b_kernel(const float* __restrict__ w0, const float* __restrict__ w1,
                               const float* __restrict__ w2, const float* __restrict__ w3,
                               __nv_bfloat16* __restrict__ hi, __nv_bfloat16* __restrict__ lo)
{
    __shared__ float t[32][33];
    int z = blockIdx.z;
    const float* W = (z == 0) ? w0 : (z == 1) ? w1 : (z == 2) ? w2 : w3;
    long long base = (long long)z * Dc * Dc;
    int n0 = blockIdx.x * 32;
    int k0 = blockIdx.y * 32;
    int tx = threadIdx.x, ty = threadIdx.y;
#pragma unroll
    for (int i = 0; i < 4; i++)
        t[ty + i * 8][tx] = W[(long long)(k0 + ty + i * 8) * Dc + n0 + tx];
    __syncthreads();
#pragma unroll
    for (int i = 0; i < 4; i++) {
        float v = t[tx][ty + i * 8];
        long long o = base + (long long)(n0 + ty + i * 8) * Dc + k0 + tx;
        __nv_bfloat16 h, l;
        split_bf16(v, h, l);
        hi[o] = h;
        lo[o] = l;
    }
}

// ---------------------------------------------------------------------------
// mma / ldmatrix helpers
// ---------------------------------------------------------------------------
__device__ __forceinline__ void mma_bf16(float* d, const unsigned* a, const unsigned* b)
{
    asm volatile(
        "mma.sync.aligned.m16n8k16.row.col.f32.bf16.bf16.f32 "
        "{%0,%1,%2,%3}, {%4,%5,%6,%7}, {%8,%9}, {%0,%1,%2,%3};"
        : "+f"(d[0]), "+f"(d[1]), "+f"(d[2]), "+f"(d[3])
        : "r"(a[0]), "r"(a[1]), "r"(a[2]), "r"(a[3]), "r"(b[0]), "r"(b[1]));
}

__device__ __forceinline__ void ldmatrix_x4(unsigned* r, unsigned addr)
{
    asm volatile("ldmatrix.sync.aligned.m8n8.x4.shared.b16 {%0,%1,%2,%3}, [%4];"
        : "=r"(r[0]), "=r"(r[1]), "=r"(r[2]), "=r"(r[3]) : "r"(addr));
}

__device__ __forceinline__ void ldmatrix_x4_trans(unsigned* r, unsigned addr)
{
    asm volatile("ldmatrix.sync.aligned.m8n8.x4.trans.shared.b16 {%0,%1,%2,%3}, [%4];"
        : "=r"(r[0]), "=r"(r[1]), "=r"(r[2]), "=r"(r[3]) : "r"(addr));
}

__device__ __forceinline__ void cpasync16(void* dst_sh, const void* src)
{
    unsigned sh = (unsigned)__cvta_generic_to_shared(dst_sh);
    asm volatile("cp.async.cg.shared.global [%0], [%1], 16;\n" :: "r"(sh), "l"(src));
}

// ---------------------------------------------------------------------------
// Shared GEMM mainloop body (bf16-split, ldmatrix fragments).
// ---------------------------------------------------------------------------
#define GS_STRIDE 40
#define GS_TILE   (128 * GS_STRIDE)
#define GS_STAGE  (4 * GS_TILE)
#define GEMM_SMEM_BYTES (2 * GS_STAGE * 2)   // 81920

__device__ __forceinline__
void gemm_mainloop(const __nv_bfloat16* Ah, const __nv_bfloat16* Al,
                   const __nv_bfloat16* Bh, const __nv_bfloat16* Bl,
                   __nv_bfloat16* smem, unsigned smem_u32,
                   int row0, int col0, float acc[4][4][4])
{
    int tid  = threadIdx.x;
    int lane = tid & 31;
    int warp = tid >> 5;
    int wm = (warp & 1) * 64;
    int wn = (warp >> 1) * 32;

    int cp_arr[8], cp_row[8], cp_c[8];
#pragma unroll
    for (int i = 0; i < 8; i++) {
        cp_arr[i] = i >> 1;
        int idx2 = ((i & 1) << 8) + tid;
        cp_row[i] = idx2 >> 2;
        cp_c[i] = (idx2 & 3) * 8;
    }

    const int nIt = Dc / 32;

    auto load_stage = [&](int it, int s) {
        __nv_bfloat16* st = smem + s * GS_STAGE;
        int k0 = it * 32;
#pragma unroll
        for (int i = 0; i < 8; i++) {
            const __nv_bfloat16* src;
            int row = cp_row[i];
            int c = cp_c[i];
            if (cp_arr[i] == 0)      src = Ah + (long long)(row0 + row) * Dc + k0 + c;
            else if (cp_arr[i] == 1) src = Al + (long long)(row0 + row) * Dc + k0 + c;
            else if (cp_arr[i] == 2) src = Bh + (long long)(col0 + row) * Dc + k0 + c;
            else                     src = Bl + (long long)(col0 + row) * Dc + k0 + c;
            cpasync16(st + cp_arr[i] * GS_TILE + row * GS_STRIDE + c, src);
        }
        asm volatile("cp.async.commit_group;\n" ::);
    };

    load_stage(0, 0);

    for (int it = 0; it < nIt; it++) {
        int buf = it & 1;
        if (it + 1 < nIt) {
            load_stage(it + 1, buf ^ 1);
            asm volatile("cp.async.wait_group 1;\n" ::);
        } else {
            asm volatile("cp.async.wait_group 0;\n" ::);
        }
        __syncthreads();

        unsigned stage_base = smem_u32 + (unsigned)(buf * GS_STAGE * 2);
        unsigned uAh = stage_base;
        unsigned uAl = stage_base + GS_TILE * 2;
        unsigned uBh = stage_base + 2 * GS_TILE * 2;
        unsigned uBl = stage_base + 3 * GS_TILE * 2;

#pragma unroll
        for (int kk = 0; kk < 32; kk += 16) {
            unsigned a_h[4][4], a_l[4][4];
#pragma unroll
            for (int im = 0; im < 4; im++) {
                int row = wm + im * 16 + (lane & 15);
                int col = kk + 8 * (lane >> 4);
                unsigned off = (unsigned)(row * GS_STRIDE + col) * 2;
                ldmatrix_x4(a_h[im], uAh + off);
                ldmatrix_x4(a_l[im], uAl + off);
            }
            unsigned b_h[4][2], b_l[4][2];
#pragma unroll
            for (int nt = 0; nt < 2; nt++) {
                int row = wn + nt * 16 + (lane & 7) + 8 * (lane >> 4);
                int col = kk + 8 * ((lane >> 3) & 1);
                unsigned off = (unsigned)(row * GS_STRIDE + col) * 2;
                unsigned th[4], tl[4];
                ldmatrix_x4(th, uBh + off);
                ldmatrix_x4(tl, uBl + off);
                b_h[2*nt][0] = th[0];   b_h[2*nt][1] = th[1];
                b_h[2*nt+1][0] = th[2]; b_h[2*nt+1][1] = th[3];
                b_l[2*nt][0] = tl[0];   b_l[2*nt][1] = tl[1];
                b_l[2*nt+1][0] = tl[2]; b_l[2*nt+1][1] = tl[3];
            }
#pragma unroll
            for (int im = 0; im < 4; im++)
#pragma unroll
                for (int in_ = 0; in_ < 4; in_++) {
                    mma_bf16(acc[im][in_], a_h[im], b_h[in_]);
                    mma_bf16(acc[im][in_], a_h[im], b_l[in_]);
                    mma_bf16(acc[im][in_], a_l[im], b_h[in_]);
                }
        }
        __syncthreads();
    }
}

// ---------------------------------------------------------------------------
// Projection GEMM: 3 z-slices, epilogue writes bf16 hi/lo QKV
// ---------------------------------------------------------------------------
__global__ __launch_bounds__(256)
void gemm_proj_kernel(const __nv_bfloat16* __restrict__ Ah, const __nv_bfloat16* __restrict__ Al,
                      const __nv_bfloat16* __restrict__ Bh, const __nv_bfloat16* __restrict__ Bl,
                      __nv_bfloat16* Chi, __nv_bfloat16* Clo,
                      const float* b0, const float* b1, const float* b2)
{
    extern __shared__ __nv_bfloat16 smem[];
    unsigned smem_u32 = (unsigned)__cvta_generic_to_shared(smem);
    int z = blockIdx.z;
    const long long aStride = (long long)M_PROJ * Dc;
    const long long bStride = (long long)Dc * Dc;
    Ah += z * aStride; Al += z * aStride;
    Bh += z * bStride; Bl += z * bStride;
    const float* bias = (z == 0) ? b0 : (z == 1) ? b1 : b2;

    int lane = threadIdx.x & 31;
    int warp = threadIdx.x >> 5;
    int wm = (warp & 1) * 64;
    int wn = (warp >> 1) * 32;
    int row0 = blockIdx.y * 128;
    int col0 = blockIdx.x * 128;

    float acc[4][4][4];
#pragma unroll
    for (int im = 0; im < 4; im++)
#pragma unroll
        for (int in_ = 0; in_ < 4; in_++)
#pragma unroll
            for (int r = 0; r < 4; r++) acc[im][in_][r] = 0.f;

    gemm_mainloop(Ah, Al, Bh, Bl, smem, smem_u32, row0, col0, acc);

    long long cb = (long long)z * aStride;
#pragma unroll
    for (int im = 0; im < 4; im++) {
#pragma unroll
        for (int in_ = 0; in_ < 4; in_++) {
            int row = row0 + wm + im * 16 + (lane >> 2);
            int col = col0 + wn + in_ * 8 + 2 * (lane & 3);
            float2 bv = *(const float2*)&bias[col];
            float o0 = acc[im][in_][0] + bv.x, o1 = acc[im][in_][1] + bv.y;
            float o2 = acc[im][in_][2] + bv.x, o3 = acc[im][in_][3] + bv.y;
            __nv_bfloat16 h0, l0, h1, l1, h2, l2, h3, l3;
            split_bf16(o0, h0, l0); split_bf16(o1, h1, l1);
            split_bf16(o2, h2, l2); split_bf16(o3, h3, l3);
            *(__nv_bfloat162*)&Chi[cb + (long long)row * Dc + col]       = __nv_bfloat162(h0, h1);
            *(__nv_bfloat162*)&Clo[cb + (long long)row * Dc + col]       = __nv_bfloat162(l0, l1);
            *(__nv_bfloat162*)&Chi[cb + (long long)(row + 8) * Dc + col] = __nv_bfloat162(h2, h3);
            *(__nv_bfloat162*)&Clo[cb + (long long)(row + 8) * Dc + col] = __nv_bfloat162(l2, l3);
        }
    }
}

// ---------------------------------------------------------------------------
// Out GEMM: fp32 epilogue (grid (4, 64))
// ---------------------------------------------------------------------------
__global__ __launch_bounds__(256)
void gemm_out_kernel(const __nv_bfloat16* __restrict__ Ah, const __nv_bfloat16* __restrict__ Al,
                     const __nv_bfloat16* __restrict__ Bh, const __nv_bfloat16* __restrict__ Bl,
                     float* __restrict__ C, const float* __restrict__ bias)
{
    extern __shared__ __nv_bfloat16 smem[];
    unsigned smem_u32 = (unsigned)__cvta_generic_to_shared(smem);
    int lane = threadIdx.x & 31;
    int warp = threadIdx.x >> 5;
    int wm = (warp & 1) * 64;
    int wn = (warp >> 1) * 32;
    int row0 = blockIdx.y * 128;
    int col0 = blockIdx.x * 128;

    float acc[4][4][4];
#pragma unroll
    for (int im = 0; im < 4; im++)
#pragma unroll
        for (int in_ = 0; in_ < 4; in_++)
#pragma unroll
            for (int r = 0; r < 4; r++) acc[im][in_][r] = 0.f;

    gemm_mainloop(Ah, Al, Bh, Bl, smem, smem_u32, row0, col0, acc);

#pragma unroll
    for (int im = 0; im < 4; im++) {
#pragma unroll
        for (int in_ = 0; in_ < 4; in_++) {
            int row = row0 + wm + im * 16 + (lane >> 2);
            int col = col0 + wn + in_ * 8 + 2 * (lane & 3);
            float2 bv = *(const float2*)&bias[col];
            *(float2*)&C[(long long)row * Dc + col] =
                make_float2(acc[im][in_][0] + bv.x, acc[im][in_][1] + bv.y);
            *(float2*)&C[(long long)(row + 8) * Dc + col] =
                make_float2(acc[im][in_][2] + bv.x, acc[im][in_][3] + bv.y);
        }
    }
}

// ---------------------------------------------------------------------------
// Dense-A writer (standalone, no smem, full occupancy): 4 rows/block.
// ---------------------------------------------------------------------------
__global__ __launch_bounds__(256)
void write_A_kernel(const float* __restrict__ Pwin, float* __restrict__ A1)
{
    int j0 = threadIdx.x * 4;
    long long r0 = (long long)blockIdx.x * 4;
    float4 z4 = make_float4(0.f, 0.f, 0.f, 0.f);
#pragma unroll
    for (int rr = 0; rr < 4; rr++) {
        long long r = r0 + rr;
        int i = (int)(r & (Pc - 1));
        int k0w = ((i >> 6) << 6) - HALFW;
        float4 v = z4;
        if (j0 >= k0w && j0 < k0w + 128)
            v = *(const float4*)&Pwin[r * 128 + (j0 - k0w)];
        __stcs((float4*)&A1[r * Pc + j0], v);
    }
}

// ---------------------------------------------------------------------------
// Tensor-core banded attention (unchanged; writes compact Pwin). 54us measured.
// ---------------------------------------------------------------------------
#define AT_STRIDE 72
#define AS_STRIDE 132
#define AP_STRIDE 136
#define O_QH 0
#define O_QL 9216
#define O_KH 18432
#define O_KL 36864
#define O_PH 0
#define O_PL 17408
#define O_SS 55296
#define O_VH 55296
#define O_VL 73728
#define O_SINV 92160
#define ATTN_SMEM_BYTES 92416

__global__ __launch_bounds__(256, 2)
void attn_mma_kernel(const __nv_bfloat16* __restrict__ QKVhi,
                     const __nv_bfloat16* __restrict__ QKVlo,
                     __nv_bfloat16* __restrict__ Chi, __nv_bfloat16* __restrict__ Clo,
                     float* __restrict__ Pwin, int writeWin)
{
    extern __shared__ char smraw[];
    __nv_bfloat16* sQh = (__nv_bfloat16*)(smraw + O_QH);
    __nv_bfloat16* sQl = (__nv_bfloat16*)(smraw + O_QL);
    __nv_bfloat16* sKh = (__nv_bfloat16*)(smraw + O_KH);
    __nv_bfloat16* sKl = (__nv_bfloat16*)(smraw + O_KL);
    float*         sS  = (float*)(smraw + O_SS);
    __nv_bfloat16* sPh = (__nv_bfloat16*)(smraw + O_PH);
    __nv_bfloat16* sPl = (__nv_bfloat16*)(smraw + O_PL);
    __nv_bfloat16* sVh = (__nv_bfloat16*)(smraw + O_VH);
    __nv_bfloat16* sVl = (__nv_bfloat16*)(smraw + O_VL);
    float*         sinv = (float*)(smraw + O_SINV);
    unsigned smem_u32 = (unsigned)__cvta_generic_to_shared(smraw);

    int tid  = threadIdx.x;
    int lane = tid & 31;
    int warp = tid >> 5;
    int q0 = blockIdx.x * 64;
    int h  = blockIdx.y;
    int zz = blockIdx.z;
    int b  = zz >> 1;
    int which = zz & 1;
    int k0 = q0 - HALFW;
    const float scale = 0.125f;

    const long long plane = (long long)M_PROJ * Dc;
    const __nv_bfloat16 *Qh, *Ql, *Kh, *Kl, *Vh, *Vl;
    int rowOffset;
    if (which == 0) {
        Qh = QKVhi;           Ql = QKVlo;
        Kh = QKVhi + plane;   Kl = QKVlo + plane;
        Vh = QKVhi + 2*plane; Vl = QKVlo + 2*plane;
        rowOffset = 0;
    } else {
        Qh = QKVhi + plane;   Ql = QKVlo + plane;
        Kh = QKVhi;           Kl = QKVlo;
        Vh = QKVhi;           Vl = QKVlo;
        rowOffset = Pc;
    }
    long long headBase = (long long)b * Pc * Dc + (long long)h * DKc;
    const uint4 zero4 = make_uint4(0, 0, 0, 0);

    for (int t = tid; t < 512; t += 256) {
        int r = t >> 3, c = (t & 7) * 8;
        long long src = headBase + (long long)(q0 + r) * Dc + c;
        *(uint4*)&sQh[r * AT_STRIDE + c] = *(const uint4*)&Qh[src];
        *(uint4*)&sQl[r * AT_STRIDE + c] = *(const uint4*)&Ql[src];
    }
    for (int t = tid; t < 1024; t += 256) {
        int r = t >> 3, c = (t & 7) * 8;
        int j = k0 + r;
        uint4 kh = zero4, kl = zero4;
        if (j >= 0 && j < Pc) {
            long long src = headBase + (long long)j * Dc + c;
            kh = *(const uint4*)&Kh[src];
            kl = *(const uint4*)&Kl[src];
        }
        *(uint4*)&sKh[r * AT_STRIDE + c] = kh;
        *(uint4*)&sKl[r * AT_STRIDE + c] = kl;
    }
    __syncthreads();

    int m0 = (warp & 1) * 32;

    // ---- S = Q*K^T ----
    {
        int n0w = (warp >> 1) * 32;
        float sacc[2][4][4];
#pragma unroll
        for (int mi = 0; mi < 2; mi++)
#pragma unroll
            for (int ni = 0; ni < 4; ni++)
#pragma unroll
                for (int r = 0; r < 4; r++) sacc[mi][ni][r] = 0.f;

#pragma unroll
        for (int ks = 0; ks < 4; ks++) {
            int kc = ks * 16;
            unsigned ah[2][4], al[2][4];
#pragma unroll
            for (int mi = 0; mi < 2; mi++) {
                int row = m0 + mi * 16 + (lane & 15);
                int col = kc + 8 * (lane >> 4);
                unsigned off = (unsigned)(row * AT_STRIDE + col) * 2;
                ldmatrix_x4(ah[mi], smem_u32 + O_QH + off);
                ldmatrix_x4(al[mi], smem_u32 + O_QL + off);
            }
            unsigned bh[4][2], bl[4][2];
#pragma unroll
            for (int nt = 0; nt < 2; nt++) {
                int row = n0w + nt * 16 + (lane & 7) + 8 * (lane >> 4);
                int col = kc + 8 * ((lane >> 3) & 1);
                unsigned off = (unsigned)(row * AT_STRIDE + col) * 2;
                unsigned th[4], tl[4];
                ldmatrix_x4(th, smem_u32 + O_KH + off);
                ldmatrix_x4(tl, smem_u32 + O_KL + off);
                bh[2*nt][0] = th[0]; bh[2*nt][1] = th[1];
                bh[2*nt+1][0] = th[2]; bh[2*nt+1][1] = th[3];
                bl[2*nt][0] = tl[0]; bl[2*nt][1] = tl[1];
                bl[2*nt+1][0] = tl[2]; bl[2*nt+1][1] = tl[3];
            }
#pragma unroll
            for (int mi = 0; mi < 2; mi++)
#pragma unroll
                for (int ni = 0; ni < 4; ni++) {
                    mma_bf16(sacc[mi][ni], ah[mi], bh[ni]);
                    mma_bf16(sacc[mi][ni], ah[mi], bl[ni]);
                    mma_bf16(sacc[mi][ni], al[mi], bh[ni]);
                }
        }
#pragma unroll
        for (int mi = 0; mi < 2; mi++)
#pragma unroll
            for (int ni = 0; ni < 4; ni++) {
                int r = m0 + mi * 16 + (lane >> 2);
                int cc = n0w + ni * 8 + 2 * (lane & 3);
                *(float2*)&sS[r * AS_STRIDE + cc] =
                    make_float2(sacc[mi][ni][0], sacc[mi][ni][1]);
                *(float2*)&sS[(r + 8) * AS_STRIDE + cc] =
                    make_float2(sacc[mi][ni][2], sacc[mi][ni][3]);
            }
    }
    __syncthreads();

    // ---- softmax ----
    {
        int qi = tid >> 2;
        int p  = tid & 3;
        int i_glob = q0 + qi;
        int jlo = i_glob - HALFW; if (jlo < 0) jlo = 0;
        int jhi = i_glob + HALFW; if (jhi > Pc - 1) jhi = Pc - 1;
        int kjlo = jlo - k0;
        int kjhi = jhi - k0;
        float* srow = &sS[qi * AS_STRIDE];
        float m = -1e30f;
#pragma unroll 8
        for (int t = 0; t < 32; t++) {
            int kj = p + 4 * t;
            if (kj >= kjlo && kj <= kjhi) m = fmaxf(m, srow[kj]);
        }
        m = fmaxf(m, __shfl_xor_sync(0xffffffffu, m, 1));
        m = fmaxf(m, __shfl_xor_sync(0xffffffffu, m, 2));
        float sum = 0.f;
#pragma unroll 8
        for (int t = 0; t < 32; t++) {
            int kj = p + 4 * t;
            float pv = 0.f;
            if (kj >= kjlo && kj <= kjhi) {
                pv = __expf(scale * (srow[kj] - m));
                sum += pv;
            }
            srow[kj] = pv;
            __nv_bfloat16 hh, ll;
            split_bf16(pv, hh, ll);
            sPh[qi * AP_STRIDE + kj] = hh;
            sPl[qi * AP_STRIDE + kj] = ll;
        }
        sum += __shfl_xor_sync(0xffffffffu, sum, 1);
        sum += __shfl_xor_sync(0xffffffffu, sum, 2);
        if (p == 0) sinv[qi] = 1.0f / sum;
    }
    __syncthreads();

    // ---- compact Pwin write ----
    if (writeWin) {
        long long prBase = ((long long)which * Bc * Hc + (long long)b * Hc + h) * Pc + q0;
        for (int t = tid; t < 64 * 32; t += 256) {
            int row = t >> 5;
            int c4  = (t & 31) * 4;
            float inv = sinv[row];
            const float* srow = &sS[row * AS_STRIDE];
            float4 v = make_float4(srow[c4] * inv, srow[c4 + 1] * inv,
                                   srow[c4 + 2] * inv, srow[c4 + 3] * inv);
            __stcs((float4*)&Pwin[(prBase + row) * 128 + c4], v);
        }
    }
    __syncthreads();

    // ---- V load over dead S region ----
    for (int t = tid; t < 1024; t += 256) {
        int r = t >> 3, c = (t & 7) * 8;
        int j = k0 + r;
        uint4 vh = zero4, vl = zero4;
        if (j >= 0 && j < Pc) {
            long long src = headBase + (long long)j * Dc + c;
            vh = *(const uint4*)&Vh[src];
            vl = *(const uint4*)&Vl[src];
        }
        *(uint4*)&sVh[r * AT_STRIDE + c] = vh;
        *(uint4*)&sVl[r * AT_STRIDE + c] = vl;
    }
    __syncthreads();

    // ---- O = P*V ----
    {
        int n0o = (warp >> 1) * 16;
        float oacc[2][2][4];
#pragma unroll
        for (int mi = 0; mi < 2; mi++)
#pragma unroll
            for (int ni = 0; ni < 2; ni++)
#pragma unroll
                for (int r = 0; r < 4; r++) oacc[mi][ni][r] = 0.f;

#pragma unroll
        for (int ks = 0; ks < 8; ks++) {
            int kc = ks * 16;
            unsigned ah[2][4], al[2][4];
#pragma unroll
            for (int mi = 0; mi < 2; mi++) {
                int row = m0 + mi * 16 + (lane & 15);
                int col = kc + 8 * (lane >> 4);
                unsigned off = (unsigned)(row * AP_STRIDE + col) * 2;
                ldmatrix_x4(ah[mi], smem_u32 + O_PH + off);
                ldmatrix_x4(al[mi], smem_u32 + O_PL + off);
            }
            unsigned bh[2][2], bl[2][2];
            {
                int row = kc + (lane & 15);
                int col = n0o + 8 * (lane >> 4);
                unsigned off = (unsigned)(row * AT_STRIDE + col) * 2;
                unsigned th[4], tl[4];
                ldmatrix_x4_trans(th, smem_u32 + O_VH + off);
                ldmatrix_x4_trans(tl, smem_u32 + O_VL + off);
                bh[0][0] = th[0]; bh[0][1] = th[1];
                bh[1][0] = th[2]; bh[1][1] = th[3];
                bl[0][0] = tl[0]; bl[0][1] = tl[1];
                bl[1][0] = tl[2]; bl[1][1] = tl[3];
            }
#pragma unroll
            for (int mi = 0; mi < 2; mi++)
#pragma unroll
                for (int ni = 0; ni < 2; ni++) {
                    mma_bf16(oacc[mi][ni], ah[mi], bh[ni]);
                    mma_bf16(oacc[mi][ni], ah[mi], bl[ni]);
                    mma_bf16(oacc[mi][ni], al[mi], bh[ni]);
                }
        }

#pragma unroll
        for (int mi = 0; mi < 2; mi++)
#pragma unroll
            for (int ni = 0; ni < 2; ni++) {
                int qi0 = m0 + mi * 16 + (lane >> 2);
                int d   = n0o + ni * 8 + 2 * (lane & 3);
                float inv0 = sinv[qi0];
                float inv1 = sinv[qi0 + 8];
                float o0 = oacc[mi][ni][0] * inv0, o1 = oacc[mi][ni][1] * inv0;
                float o2 = oacc[mi][ni][2] * inv1, o3 = oacc[mi][ni][3] * inv1;
                long long dst0 = ((long long)b * CONCAT_P + rowOffset + q0 + qi0) * Dc
                                 + h * DKc + d;
                long long dst1 = dst0 + 8LL * Dc;
                __nv_bfloat16 h0, l0, h1, l1, h2, l2, h3, l3;
                split_bf16(o0, h0, l0); split_bf16(o1, h1, l1);
                split_bf16(o2, h2, l2); split_bf16(o3, h3, l3);
                *(__nv_bfloat162*)&Chi[dst0] = __nv_bfloat162(h0, h1);
                *(__nv_bfloat162*)&Clo[dst0] = __nv_bfloat162(l0, l1);
                *(__nv_bfloat162*)&Chi[dst1] = __nv_bfloat162(h2, h3);
                *(__nv_bfloat162*)&Clo[dst1] = __nv_bfloat162(l2, l3);
            }
    }
}

// ---------------------------------------------------------------------------
extern "C" void kernel_launch(void* const* d_in, const int* in_sizes, int n_in,
                              void* d_out, int out_size)
{
    const float* queries = (const float*)d_in[0];
    const float* keys    = (const float*)d_in[1];
    const float* values  = (const float*)d_in[2];
    const float* Wq = (const float*)d_in[3];
    const float* bq = (const float*)d_in[4];
    const float* Wk = (const float*)d_in[5];
    const float* bk = (const float*)d_in[6];
    const float* Wv = (const float*)d_in[7];
    const float* bv = (const float*)d_in[8];
    const float* Wo = (const float*)d_in[9];
    const float* bo = (const float*)d_in[10];

    float* out = (float*)d_out;

    __nv_bfloat16 *Ahi, *Alo, *Bhi, *Blo, *QKVhi, *QKVlo, *Chi, *Clo;
    float* Pwin;
    cudaGetSymbolAddress((void**)&Ahi, g_Ahi);
    cudaGetSymbolAddress((void**)&Alo, g_Alo);
    cudaGetSymbolAddress((void**)&Bhi, g_Bhi);
    cudaGetSymbolAddress((void**)&Blo, g_Blo);
    cudaGetSymbolAddress((void**)&QKVhi, g_QKVhi);
    cudaGetSymbolAddress((void**)&QKVlo, g_QKVlo);
    cudaGetSymbolAddress((void**)&Chi, g_Chi);
    cudaGetSymbolAddress((void**)&Clo, g_Clo);
    cudaGetSymbolAddress((void**)&Pwin, g_Pwin);

    static int attr_set = 0;
    static cudaStream_t sW = nullptr;
    static cudaEvent_t evAttn = nullptr, evW = nullptr;
    if (!attr_set) {
        cudaFuncSetAttribute(attn_mma_kernel,
                             cudaFuncAttributeMaxDynamicSharedMemorySize, ATTN_SMEM_BYTES);
        cudaFuncSetAttribute(gemm_proj_kernel,
                             cudaFuncAttributeMaxDynamicSharedMemorySize, GEMM_SMEM_BYTES);
        cudaFuncSetAttribute(gemm_out_kernel,
                             cudaFuncAttributeMaxDynamicSharedMemorySize, GEMM_SMEM_BYTES);
        cudaStreamCreateWithFlags(&sW, cudaStreamNonBlocking);
        cudaEventCreateWithFlags(&evAttn, cudaEventDisableTiming);
        cudaEventCreateWithFlags(&evW, cudaEventDisableTiming);
        attr_set = 1;
    }

    const long long mainN = (long long)M_OUT * Dc;
    const long long aN    = (long long)Bc * Hc * Pc * Pc;
    float* A1 = nullptr;
    bool hasA = ((long long)out_size >= mainN + 2 * aN);
    if (hasA) A1 = out + mainN;      // A2 contiguous after A1; writer covers both

    split_a_kernel<<<dim3(256, 1, 3), 256>>>(queries, keys, values, Ahi, Alo);
    split_b_kernel<<<dim3(16, 16, 4), dim3(32, 8)>>>(Wq, Wk, Wv, Wo, Bhi, Blo);

    const long long bStride = (long long)Dc * Dc;

    gemm_proj_kernel<<<dim3(Dc / 128, M_PROJ / 128, 3), 256, GEMM_SMEM_BYTES>>>(
        Ahi, Alo, Bhi, Blo, QKVhi, QKVlo, bq, bk, bv);

    dim3 ga(Pc / 64, Hc, Bc * 2);
    attn_mma_kernel<<<ga, 256, ATTN_SMEM_BYTES>>>(QKVhi, QKVlo, Chi, Clo,
                                                  Pwin, hasA ? 1 : 0);

    if (hasA) {
        // fork: dense-A writer on side stream, out-GEMM on main stream
        cudaEventRecord(evAttn, 0);
        cudaStreamWaitEvent(sW, evAttn, 0);
        write_A_kernel<<<NROWS / 4, 256, 0, sW>>>(Pwin, A1);
        gemm_out_kernel<<<dim3(Dc / 128, M_OUT / 128), 256, GEMM_SMEM_BYTES>>>(
            Chi, Clo, Bhi + 3 * bStride, Blo + 3 * bStride, out, bo);
        // join
        cudaEventRecord(evW, sW);
        cudaStreamWaitEvent(0, evW, 0);
    } else {
        gemm_out_kernel<<<dim3(Dc / 128, M_OUT / 128), 256, GEMM_SMEM_BYTES>>>(
            Chi, Clo, Bhi + 3 * bStride, Blo + 3 * bStride, out, bo);
    }
}